// round 1
// baseline (speedup 1.0000x reference)
#include <cuda_runtime.h>

// Problem constants
#define T_   256
#define N_   4096
#define C_   12
#define D_   256
#define K_   12

// Kernel config
#define RB     32          // rows per block
#define NTHR   256
#define NBLK   (N_ / RB)   // 128
#define KC     32          // k-chunk size
#define NCHUNK (D_ / KC)   // 8

// Shared memory layout (in floats)
#define OFF_HDUP 0
#define SZ_HDUP  (D_ * 2 * RB)            // hdup[k][2r], 256*64 = 16384
#define OFF_SW   (OFF_HDUP + SZ_HDUP)
#define SZ_SW    (2 * KC * D_)            // double-buffered transposed W chunk
#define OFF_SWX  (OFF_SW + SZ_SW)         // sWx[c][d]  12*256
#define OFF_SWY  (OFF_SWX + C_ * D_)      // sWy[k][d]  12*256
#define OFF_SBX  (OFF_SWY + K_ * D_)      // 256
#define OFF_SBY  (OFF_SBX + D_)           // 16 (padded)
#define OFF_SXD  (OFF_SBY + 16)           // sxd[r][2c] duplicated x, 32*24
#define OFF_YTMP (OFF_SXD + RB * 24)      // ytmp[r][12]
#define OFF_SSEL (OFF_YTMP + RB * K_)     // RB ints
#define SMEM_FLOATS (OFF_SSEL + RB)
#define SMEM_BYTES  (SMEM_FLOATS * 4)

__device__ __forceinline__ void ffma2(unsigned long long &d,
                                      unsigned long long a,
                                      unsigned long long b) {
    asm("fma.rn.f32x2 %0, %1, %2, %0;" : "+l"(d) : "l"(a), "l"(b));
}
__device__ __forceinline__ unsigned long long add2(unsigned long long a,
                                                   unsigned long long b) {
    unsigned long long r;
    asm("add.rn.f32x2 %0, %1, %2;" : "=l"(r) : "l"(a), "l"(b));
    return r;
}
__device__ __forceinline__ void unpack2(unsigned long long v, float &lo, float &hi) {
    asm("mov.b64 {%0, %1}, %2;" : "=f"(lo), "=f"(hi) : "l"(v));
}

extern "C" __global__ void __launch_bounds__(NTHR, 1)
seq2seq_persistent_kernel(const float* __restrict__ x,
                          const float* __restrict__ eWx, const float* __restrict__ ebx,
                          const float* __restrict__ eWh,
                          const float* __restrict__ dWx, const float* __restrict__ dbx,
                          const float* __restrict__ dWh,
                          const float* __restrict__ dWy, const float* __restrict__ dby,
                          float* __restrict__ out)
{
    extern __shared__ float sm[];
    float* hdup = sm + OFF_HDUP;   // hdup[k][2r] = {h[r][k], h[r][k]}
    float* sW   = sm + OFF_SW;     // sW[buf][kk][d] transposed Wh chunk
    float* sWx  = sm + OFF_SWX;    // [c][d]
    float* sWy  = sm + OFF_SWY;    // [kk][d]
    float* sbx  = sm + OFF_SBX;
    float* sby  = sm + OFF_SBY;
    float* sxd  = sm + OFF_SXD;    // [r][2c] duplicated x slice
    float* ytmp = sm + OFF_YTMP;   // [r][12]
    int*   ssel = (int*)(sm + OFF_SSEL);

    const int tid  = threadIdx.x;
    const int lane = tid & 31;
    const int warp = tid >> 5;
    const int rowbase = blockIdx.x * RB;

    // compute mapping: warp owns d in [32*warp, 32*warp+32)
    // within warp: d_sub = lane>>3 (4 groups of 8 d), r_grp = lane&7 (8 groups of 4 rows)
    const int d0 = warp * 32 + (lane >> 3) * 8;
    const int r0 = (lane & 7) * 4;

    // ---- init ----
    for (int i = tid; i < SZ_HDUP; i += NTHR) hdup[i] = 0.f;
    for (int i = tid; i < D_ * C_; i += NTHR) {
        int d = i / C_, c = i % C_;
        sWx[c * D_ + d] = eWx[i];
    }
    for (int i = tid; i < K_ * D_; i += NTHR) sWy[i] = dWy[i];
    if (tid < D_) sbx[tid] = ebx[tid];
    if (tid < K_) sby[tid] = dby[tid];
    __syncthreads();

    unsigned long long acc[16];   // acc[i*4 + j2] : row r0+i, d pair (d0+2j2, d0+2j2+1)
    float4 pf[8];                 // W chunk prefetch registers

    for (int t = 0; t < 2 * T_; ++t) {
        const bool dec = (t >= T_);

        if (t == T_) {
            // switch input-projection weights to decoder; init sos index (C-2)
            for (int i = tid; i < D_ * C_; i += NTHR) {
                int d = i / C_, c = i % C_;
                sWx[c * D_ + d] = dWx[i];
            }
            if (tid < D_) sbx[tid] = dbx[tid];
            if (tid < RB) ssel[tid] = C_ - 2;
        }

        // stage x slice for encoder step (duplicated pairs)
        if (!dec) {
            const float* xg = x + ((size_t)t * N_ + rowbase) * C_;
            for (int i = tid; i < RB * C_; i += NTHR) {
                float v = xg[i];
                int r = i / C_, c = i % C_;
                sxd[r * 24 + 2 * c]     = v;
                sxd[r * 24 + 2 * c + 1] = v;
            }
        }

        const float* Wsrc = dec ? dWh : eWh;

        // prefetch W chunk 0 into registers (row d = tid, k in [0,32))
        {
            const float4* gp = (const float4*)(Wsrc + (size_t)tid * D_);
            #pragma unroll
            for (int i2 = 0; i2 < 8; ++i2) pf[i2] = gp[i2];
        }

        __syncthreads();   // (1) sxd / sWx / ssel / prev hdup all visible

        // store chunk 0 transposed: sW[kk][d]
        #pragma unroll
        for (int i2 = 0; i2 < 8; ++i2) {
            float4 v = pf[i2];
            sW[(4 * i2 + 0) * D_ + tid] = v.x;
            sW[(4 * i2 + 1) * D_ + tid] = v.y;
            sW[(4 * i2 + 2) * D_ + tid] = v.z;
            sW[(4 * i2 + 3) * D_ + tid] = v.w;
        }

        // ---- accumulator init: xp = bias + input projection ----
        {
            ulonglong2 b01 = *(const ulonglong2*)(sbx + d0);
            ulonglong2 b23 = *(const ulonglong2*)(sbx + d0 + 4);
            if (!dec) {
                #pragma unroll
                for (int i = 0; i < 4; ++i) {
                    acc[i * 4 + 0] = b01.x; acc[i * 4 + 1] = b01.y;
                    acc[i * 4 + 2] = b23.x; acc[i * 4 + 3] = b23.y;
                }
                #pragma unroll
                for (int c = 0; c < C_; ++c) {
                    ulonglong2 w01 = *(const ulonglong2*)(sWx + c * D_ + d0);
                    ulonglong2 w23 = *(const ulonglong2*)(sWx + c * D_ + d0 + 4);
                    #pragma unroll
                    for (int i = 0; i < 4; ++i) {
                        unsigned long long xv =
                            *(const unsigned long long*)(sxd + (r0 + i) * 24 + 2 * c);
                        ffma2(acc[i * 4 + 0], xv, w01.x);
                        ffma2(acc[i * 4 + 1], xv, w01.y);
                        ffma2(acc[i * 4 + 2], xv, w23.x);
                        ffma2(acc[i * 4 + 3], xv, w23.y);
                    }
                }
            } else {
                #pragma unroll
                for (int i = 0; i < 4; ++i) {
                    int s = ssel[r0 + i];     // one-hot feedback -> column gather
                    ulonglong2 w01 = *(const ulonglong2*)(sWx + s * D_ + d0);
                    ulonglong2 w23 = *(const ulonglong2*)(sWx + s * D_ + d0 + 4);
                    acc[i * 4 + 0] = add2(b01.x, w01.x);
                    acc[i * 4 + 1] = add2(b01.y, w01.y);
                    acc[i * 4 + 2] = add2(b23.x, w23.x);
                    acc[i * 4 + 3] = add2(b23.y, w23.y);
                }
            }
        }

        __syncthreads();   // (2) chunk 0 in smem

        // ---- main GEMM: acc += h @ Wh^T, k-chunked, double buffered ----
        #pragma unroll 1
        for (int c = 0; c < NCHUNK; ++c) {
            if (c < NCHUNK - 1) {
                const float4* gp =
                    (const float4*)(Wsrc + (size_t)tid * D_ + (c + 1) * KC);
                #pragma unroll
                for (int i2 = 0; i2 < 8; ++i2) pf[i2] = gp[i2];
            }
            const float* sWc = sW + (c & 1) * (KC * D_);
            const float* hp0 = hdup + (c * KC) * (2 * RB) + 2 * r0;
            #pragma unroll 4
            for (int kk = 0; kk < KC; ++kk) {
                ulonglong2 w01 = *(const ulonglong2*)(sWc + kk * D_ + d0);
                ulonglong2 w23 = *(const ulonglong2*)(sWc + kk * D_ + d0 + 4);
                ulonglong2 hA  = *(const ulonglong2*)(hp0 + kk * (2 * RB));
                ulonglong2 hB  = *(const ulonglong2*)(hp0 + kk * (2 * RB) + 4);
                ffma2(acc[0],  hA.x, w01.x); ffma2(acc[1],  hA.x, w01.y);
                ffma2(acc[2],  hA.x, w23.x); ffma2(acc[3],  hA.x, w23.y);
                ffma2(acc[4],  hA.y, w01.x); ffma2(acc[5],  hA.y, w01.y);
                ffma2(acc[6],  hA.y, w23.x); ffma2(acc[7],  hA.y, w23.y);
                ffma2(acc[8],  hB.x, w01.x); ffma2(acc[9],  hB.x, w01.y);
                ffma2(acc[10], hB.x, w23.x); ffma2(acc[11], hB.x, w23.y);
                ffma2(acc[12], hB.y, w01.x); ffma2(acc[13], hB.y, w01.y);
                ffma2(acc[14], hB.y, w23.x); ffma2(acc[15], hB.y, w23.y);
            }
            __syncthreads();     // all reads of sW[c&1] and hdup done
            if (c < NCHUNK - 1) {
                float* dst = sW + ((c + 1) & 1) * (KC * D_);
                #pragma unroll
                for (int i2 = 0; i2 < 8; ++i2) {
                    float4 v = pf[i2];
                    dst[(4 * i2 + 0) * D_ + tid] = v.x;
                    dst[(4 * i2 + 1) * D_ + tid] = v.y;
                    dst[(4 * i2 + 2) * D_ + tid] = v.z;
                    dst[(4 * i2 + 3) * D_ + tid] = v.w;
                }
                __syncthreads();
            }
        }

        // ---- relu + store new h (transposed + duplicated) ----
        #pragma unroll
        for (int i = 0; i < 4; ++i) {
            #pragma unroll
            for (int j2 = 0; j2 < 4; ++j2) {
                float lo, hi;
                unpack2(acc[i * 4 + j2], lo, hi);
                lo = fmaxf(lo, 0.f);
                hi = fmaxf(hi, 0.f);
                int d = d0 + 2 * j2;
                int r = r0 + i;
                *(float2*)(hdup + (size_t)d * (2 * RB) + 2 * r)       = make_float2(lo, lo);
                *(float2*)(hdup + (size_t)(d + 1) * (2 * RB) + 2 * r) = make_float2(hi, hi);
            }
        }

        // ---- decoder: y = h @ Wy^T + by, argmax feedback, store output ----
        if (dec) {
            __syncthreads();   // new hdup visible
            #pragma unroll
            for (int it = 0; it < 2; ++it) {
                int kk = warp + it * 8;
                if (kk < K_) {
                    const float* wy = sWy + kk * D_;
                    const float* hc = hdup + 2 * lane;   // lane = row
                    float s = 0.f;
                    #pragma unroll 8
                    for (int d = 0; d < D_; ++d) s += hc[d * (2 * RB)] * wy[d];
                    ytmp[lane * K_ + kk] = s + sby[kk];
                }
            }
            __syncthreads();
            if (warp == 0) {
                const float* yr = ytmp + lane * K_;
                float v[12];
                #pragma unroll
                for (int q = 0; q < 3; ++q) {
                    float4 f = *(const float4*)(yr + 4 * q);
                    v[4 * q] = f.x; v[4 * q + 1] = f.y;
                    v[4 * q + 2] = f.z; v[4 * q + 3] = f.w;
                }
                float best = v[0]; int bi = 0;
                #pragma unroll
                for (int q = 1; q < 12; ++q)
                    if (v[q] > best) { best = v[q]; bi = q; }   // first-max wins
                ssel[lane] = bi;
                float* og = out + ((size_t)(t - T_) * N_ + rowbase + lane) * K_;
                *(float4*)(og)     = make_float4(v[0], v[1], v[2],  v[3]);
                *(float4*)(og + 4) = make_float4(v[4], v[5], v[6],  v[7]);
                *(float4*)(og + 8) = make_float4(v[8], v[9], v[10], v[11]);
            }
            // next iteration's barrier (1) orders ssel/ytmp for the next step
        }
    }
}

extern "C" void kernel_launch(void* const* d_in, const int* in_sizes, int n_in,
                              void* d_out, int out_size) {
    const float* x   = (const float*)d_in[0];
    const float* eWx = (const float*)d_in[1];
    const float* ebx = (const float*)d_in[2];
    const float* eWh = (const float*)d_in[3];
    // d_in[4] = enc_Wy, d_in[5] = enc_by : outputs discarded by reference, unused
    const float* dWx = (const float*)d_in[6];
    const float* dbx = (const float*)d_in[7];
    const float* dWh = (const float*)d_in[8];
    const float* dWy = (const float*)d_in[9];
    const float* dby = (const float*)d_in[10];

    cudaFuncSetAttribute(seq2seq_persistent_kernel,
                         cudaFuncAttributeMaxDynamicSharedMemorySize, SMEM_BYTES);
    seq2seq_persistent_kernel<<<NBLK, NTHR, SMEM_BYTES>>>(
        x, eWx, ebx, eWh, dWx, dbx, dWh, dWy, dby, (float*)d_out);
}

// round 2
// speedup vs baseline: 1.0006x; 1.0006x over previous
#include <cuda_runtime.h>

// Problem constants
#define T_   256
#define N_   4096
#define C_   12
#define D_   256
#define K_   12

// Kernel config
#define RB     32          // rows per block
#define NTHR   256
#define NBLK   (N_ / RB)   // 128
#define KC     32          // k-chunk size
#define NCHUNK (D_ / KC)   // 8

// Shared memory layout (in floats)
#define OFF_HDUP 0
#define SZ_HDUP  (D_ * 2 * RB)            // hdup[k][2r], 256*64 = 16384
#define OFF_SW   (OFF_HDUP + SZ_HDUP)
#define SZ_SW    (2 * KC * D_)            // double-buffered transposed W chunk
#define OFF_SWX  (OFF_SW + SZ_SW)         // sWx[c][d]  12*256
#define OFF_SWY  (OFF_SWX + C_ * D_)      // sWy[k][d]  12*256
#define OFF_SBX  (OFF_SWY + K_ * D_)      // 256
#define OFF_SBY  (OFF_SBX + D_)           // 16 (padded)
#define OFF_SXD  (OFF_SBY + 16)           // sxd[r][2c] duplicated x, 32*24
#define OFF_YTMP (OFF_SXD + RB * 24)      // ytmp[r][12]
#define OFF_SSEL (OFF_YTMP + RB * K_)     // RB ints
#define SMEM_FLOATS (OFF_SSEL + RB)
#define SMEM_BYTES  (SMEM_FLOATS * 4)

__device__ __forceinline__ void ffma2(unsigned long long &d,
                                      unsigned long long a,
                                      unsigned long long b) {
    asm("fma.rn.f32x2 %0, %1, %2, %0;" : "+l"(d) : "l"(a), "l"(b));
}
__device__ __forceinline__ unsigned long long add2(unsigned long long a,
                                                   unsigned long long b) {
    unsigned long long r;
    asm("add.rn.f32x2 %0, %1, %2;" : "=l"(r) : "l"(a), "l"(b));
    return r;
}
__device__ __forceinline__ void unpack2(unsigned long long v, float &lo, float &hi) {
    asm("mov.b64 {%0, %1}, %2;" : "=f"(lo), "=f"(hi) : "l"(v));
}

extern "C" __global__ void __launch_bounds__(NTHR, 1)
seq2seq_persistent_kernel(const float* __restrict__ x,
                          const float* __restrict__ eWx, const float* __restrict__ ebx,
                          const float* __restrict__ eWh,
                          const float* __restrict__ dWx, const float* __restrict__ dbx,
                          const float* __restrict__ dWh,
                          const float* __restrict__ dWy, const float* __restrict__ dby,
                          float* __restrict__ out)
{
    extern __shared__ float sm[];
    float* hdup = sm + OFF_HDUP;   // hdup[k][2r] = {h[r][k], h[r][k]}
    float* sW   = sm + OFF_SW;     // sW[buf][kk][d] transposed Wh chunk
    float* sWx  = sm + OFF_SWX;    // [c][d]
    float* sWy  = sm + OFF_SWY;    // [kk][d]
    float* sbx  = sm + OFF_SBX;
    float* sby  = sm + OFF_SBY;
    float* sxd  = sm + OFF_SXD;    // [r][2c] duplicated x slice
    float* ytmp = sm + OFF_YTMP;   // [r][12]
    int*   ssel = (int*)(sm + OFF_SSEL);

    const int tid  = threadIdx.x;
    const int lane = tid & 31;
    const int warp = tid >> 5;
    const int rowbase = blockIdx.x * RB;

    // compute mapping: warp owns d in [32*warp, 32*warp+32)
    // within warp: d_sub = lane>>3 (4 groups of 8 d), r_grp = lane&7 (8 groups of 4 rows)
    const int d0 = warp * 32 + (lane >> 3) * 8;
    const int r0 = (lane & 7) * 4;

    // ---- init ----
    for (int i = tid; i < SZ_HDUP; i += NTHR) hdup[i] = 0.f;
    for (int i = tid; i < D_ * C_; i += NTHR) {
        int d = i / C_, c = i % C_;
        sWx[c * D_ + d] = eWx[i];
    }
    for (int i = tid; i < K_ * D_; i += NTHR) sWy[i] = dWy[i];
    if (tid < D_) sbx[tid] = ebx[tid];
    if (tid < K_) sby[tid] = dby[tid];
    __syncthreads();

    unsigned long long acc[16];   // acc[i*4 + j2] : row r0+i, d pair (d0+2j2, d0+2j2+1)
    float4 pf[8];                 // W chunk prefetch registers

    for (int t = 0; t < 2 * T_; ++t) {
        const bool dec = (t >= T_);

        if (t == T_) {
            // switch input-projection weights to decoder; init sos index (C-2)
            for (int i = tid; i < D_ * C_; i += NTHR) {
                int d = i / C_, c = i % C_;
                sWx[c * D_ + d] = dWx[i];
            }
            if (tid < D_) sbx[tid] = dbx[tid];
            if (tid < RB) ssel[tid] = C_ - 2;
        }

        // stage x slice for encoder step (duplicated pairs)
        if (!dec) {
            const float* xg = x + ((size_t)t * N_ + rowbase) * C_;
            for (int i = tid; i < RB * C_; i += NTHR) {
                float v = xg[i];
                int r = i / C_, c = i % C_;
                sxd[r * 24 + 2 * c]     = v;
                sxd[r * 24 + 2 * c + 1] = v;
            }
        }

        const float* Wsrc = dec ? dWh : eWh;

        // prefetch W chunk 0 into registers (row d = tid, k in [0,32))
        {
            const float4* gp = (const float4*)(Wsrc + (size_t)tid * D_);
            #pragma unroll
            for (int i2 = 0; i2 < 8; ++i2) pf[i2] = gp[i2];
        }

        __syncthreads();   // (1) sxd / sWx / ssel / prev hdup all visible

        // store chunk 0 transposed: sW[kk][d]
        #pragma unroll
        for (int i2 = 0; i2 < 8; ++i2) {
            float4 v = pf[i2];
            sW[(4 * i2 + 0) * D_ + tid] = v.x;
            sW[(4 * i2 + 1) * D_ + tid] = v.y;
            sW[(4 * i2 + 2) * D_ + tid] = v.z;
            sW[(4 * i2 + 3) * D_ + tid] = v.w;
        }

        // ---- accumulator init: xp = bias + input projection ----
        {
            ulonglong2 b01 = *(const ulonglong2*)(sbx + d0);
            ulonglong2 b23 = *(const ulonglong2*)(sbx + d0 + 4);
            if (!dec) {
                #pragma unroll
                for (int i = 0; i < 4; ++i) {
                    acc[i * 4 + 0] = b01.x; acc[i * 4 + 1] = b01.y;
                    acc[i * 4 + 2] = b23.x; acc[i * 4 + 3] = b23.y;
                }
                #pragma unroll
                for (int c = 0; c < C_; ++c) {
                    ulonglong2 w01 = *(const ulonglong2*)(sWx + c * D_ + d0);
                    ulonglong2 w23 = *(const ulonglong2*)(sWx + c * D_ + d0 + 4);
                    #pragma unroll
                    for (int i = 0; i < 4; ++i) {
                        unsigned long long xv =
                            *(const unsigned long long*)(sxd + (r0 + i) * 24 + 2 * c);
                        ffma2(acc[i * 4 + 0], xv, w01.x);
                        ffma2(acc[i * 4 + 1], xv, w01.y);
                        ffma2(acc[i * 4 + 2], xv, w23.x);
                        ffma2(acc[i * 4 + 3], xv, w23.y);
                    }
                }
            } else {
                #pragma unroll
                for (int i = 0; i < 4; ++i) {
                    int s = ssel[r0 + i];     // one-hot feedback -> column gather
                    ulonglong2 w01 = *(const ulonglong2*)(sWx + s * D_ + d0);
                    ulonglong2 w23 = *(const ulonglong2*)(sWx + s * D_ + d0 + 4);
                    acc[i * 4 + 0] = add2(b01.x, w01.x);
                    acc[i * 4 + 1] = add2(b01.y, w01.y);
                    acc[i * 4 + 2] = add2(b23.x, w23.x);
                    acc[i * 4 + 3] = add2(b23.y, w23.y);
                }
            }
        }

        __syncthreads();   // (2) chunk 0 in smem

        // ---- main GEMM: acc += h @ Wh^T, k-chunked, double buffered ----
        #pragma unroll 1
        for (int c = 0; c < NCHUNK; ++c) {
            if (c < NCHUNK - 1) {
                const float4* gp =
                    (const float4*)(Wsrc + (size_t)tid * D_ + (c + 1) * KC);
                #pragma unroll
                for (int i2 = 0; i2 < 8; ++i2) pf[i2] = gp[i2];
            }
            const float* sWc = sW + (c & 1) * (KC * D_);
            const float* hp0 = hdup + (c * KC) * (2 * RB) + 2 * r0;
            #pragma unroll 4
            for (int kk = 0; kk < KC; ++kk) {
                ulonglong2 w01 = *(const ulonglong2*)(sWc + kk * D_ + d0);
                ulonglong2 w23 = *(const ulonglong2*)(sWc + kk * D_ + d0 + 4);
                ulonglong2 hA  = *(const ulonglong2*)(hp0 + kk * (2 * RB));
                ulonglong2 hB  = *(const ulonglong2*)(hp0 + kk * (2 * RB) + 4);
                ffma2(acc[0],  hA.x, w01.x); ffma2(acc[1],  hA.x, w01.y);
                ffma2(acc[2],  hA.x, w23.x); ffma2(acc[3],  hA.x, w23.y);
                ffma2(acc[4],  hA.y, w01.x); ffma2(acc[5],  hA.y, w01.y);
                ffma2(acc[6],  hA.y, w23.x); ffma2(acc[7],  hA.y, w23.y);
                ffma2(acc[8],  hB.x, w01.x); ffma2(acc[9],  hB.x, w01.y);
                ffma2(acc[10], hB.x, w23.x); ffma2(acc[11], hB.x, w23.y);
                ffma2(acc[12], hB.y, w01.x); ffma2(acc[13], hB.y, w01.y);
                ffma2(acc[14], hB.y, w23.x); ffma2(acc[15], hB.y, w23.y);
            }
            __syncthreads();     // all reads of sW[c&1] and hdup done
            if (c < NCHUNK - 1) {
                float* dst = sW + ((c + 1) & 1) * (KC * D_);
                #pragma unroll
                for (int i2 = 0; i2 < 8; ++i2) {
                    float4 v = pf[i2];
                    dst[(4 * i2 + 0) * D_ + tid] = v.x;
                    dst[(4 * i2 + 1) * D_ + tid] = v.y;
                    dst[(4 * i2 + 2) * D_ + tid] = v.z;
                    dst[(4 * i2 + 3) * D_ + tid] = v.w;
                }
                __syncthreads();
            }
        }

        // ---- relu + store new h (transposed + duplicated) ----
        #pragma unroll
        for (int i = 0; i < 4; ++i) {
            #pragma unroll
            for (int j2 = 0; j2 < 4; ++j2) {
                float lo, hi;
                unpack2(acc[i * 4 + j2], lo, hi);
                lo = fmaxf(lo, 0.f);
                hi = fmaxf(hi, 0.f);
                int d = d0 + 2 * j2;
                int r = r0 + i;
                *(float2*)(hdup + (size_t)d * (2 * RB) + 2 * r)       = make_float2(lo, lo);
                *(float2*)(hdup + (size_t)(d + 1) * (2 * RB) + 2 * r) = make_float2(hi, hi);
            }
        }

        // ---- decoder: y = h @ Wy^T + by, argmax feedback, store output ----
        if (dec) {
            __syncthreads();   // new hdup visible
            #pragma unroll
            for (int it = 0; it < 2; ++it) {
                int kk = warp + it * 8;
                if (kk < K_) {
                    const float* wy = sWy + kk * D_;
                    const float* hc = hdup + 2 * lane;   // lane = row
                    float s = 0.f;
                    #pragma unroll 8
                    for (int d = 0; d < D_; ++d) s += hc[d * (2 * RB)] * wy[d];
                    ytmp[lane * K_ + kk] = s + sby[kk];
                }
            }
            __syncthreads();
            if (warp == 0) {
                const float* yr = ytmp + lane * K_;
                float v[12];
                #pragma unroll
                for (int q = 0; q < 3; ++q) {
                    float4 f = *(const float4*)(yr + 4 * q);
                    v[4 * q] = f.x; v[4 * q + 1] = f.y;
                    v[4 * q + 2] = f.z; v[4 * q + 3] = f.w;
                }
                float best = v[0]; int bi = 0;
                #pragma unroll
                for (int q = 1; q < 12; ++q)
                    if (v[q] > best) { best = v[q]; bi = q; }   // first-max wins
                ssel[lane] = bi;
                float* og = out + ((size_t)(t - T_) * N_ + rowbase + lane) * K_;
                *(float4*)(og)     = make_float4(v[0], v[1], v[2],  v[3]);
                *(float4*)(og + 4) = make_float4(v[4], v[5], v[6],  v[7]);
                *(float4*)(og + 8) = make_float4(v[8], v[9], v[10], v[11]);
            }
            // next iteration's barrier (1) orders ssel/ytmp for the next step
        }
    }
}

extern "C" void kernel_launch(void* const* d_in, const int* in_sizes, int n_in,
                              void* d_out, int out_size) {
    const float* x   = (const float*)d_in[0];
    const float* eWx = (const float*)d_in[1];
    const float* ebx = (const float*)d_in[2];
    const float* eWh = (const float*)d_in[3];
    // d_in[4] = enc_Wy, d_in[5] = enc_by : outputs discarded by reference, unused
    const float* dWx = (const float*)d_in[6];
    const float* dbx = (const float*)d_in[7];
    const float* dWh = (const float*)d_in[8];
    const float* dWy = (const float*)d_in[9];
    const float* dby = (const float*)d_in[10];

    cudaFuncSetAttribute(seq2seq_persistent_kernel,
                         cudaFuncAttributeMaxDynamicSharedMemorySize, SMEM_BYTES);
    seq2seq_persistent_kernel<<<NBLK, NTHR, SMEM_BYTES>>>(
        x, eWx, ebx, eWh, dWx, dbx, dWh, dWy, dby, (float*)d_out);
}

// round 3
// speedup vs baseline: 2.1335x; 2.1321x over previous
#include <cuda_runtime.h>
#include <cstdint>

#define T_    256
#define N_    4096
#define C_    12
#define D_    256
#define K_    12
#define KPAD  136          // 272/2 k-pairs: 128 h-pairs + 6 x-pairs + 2 zero pad
#define RB    32           // rows per CTA
#define NTHR  256
#define NBLK  (N_ / RB)    // 128
#define CH    17           // k-pairs per TMA chunk; 8 chunks = 136
#define NCHK  8
#define CHBYTES (CH * D_ * 8)   // 34816

typedef unsigned long long ull;

// ---- shared layout (float offsets) ----
#define OFF_SW   0
#define SZ_SW    (2 * CH * D_ * 2)          // 2 buffers of [17][256] float2
#define OFF_SH   (OFF_SW + SZ_SW)           // h_aug: [136][32] float2
#define SZ_SH    (KPAD * RB * 2)
#define OFF_SWY  (OFF_SH + SZ_SH)           // Wy raw [12][256] floats (== paired image)
#define OFF_SBX  (OFF_SWY + K_ * D_)        // sbx2[d] = {bx[d],0} : 256 float2
#define OFF_SBY  (OFF_SBX + 2 * D_)
#define OFF_YT   (OFF_SBY + 16)             // ytmp[32][12]
#define OFF_MB   (OFF_YT + RB * K_)         // 2 mbarriers
#define SMEM_FLOATS (OFF_MB + 8)
#define SMEM_BYTES  (SMEM_FLOATS * 4)

// W pre-paired: g_Wp[phase][kp][d] = {W(d,2kp), W(d,2kp+1)}; kp>=128 -> Wx cols; kp>=134 -> 0
__device__ float2 g_Wp[2][KPAD][D_];

__device__ __forceinline__ void ffma2(ull &d, ull a, ull b) {
    asm("fma.rn.f32x2 %0, %1, %2, %0;" : "+l"(d) : "l"(a), "l"(b));
}
__device__ __forceinline__ void unpack2(ull v, float &lo, float &hi) {
    asm("mov.b64 {%0, %1}, %2;" : "=f"(lo), "=f"(hi) : "l"(v));
}
__device__ __forceinline__ unsigned smem_u32(const void* p) {
    unsigned r;
    asm("{ .reg .u64 t; cvta.to.shared.u64 t, %1; cvt.u32.u64 %0, t; }" : "=r"(r) : "l"(p));
    return r;
}
__device__ __forceinline__ void mbar_init(unsigned mb, unsigned cnt) {
    asm volatile("mbarrier.init.shared.b64 [%0], %1;" :: "r"(mb), "r"(cnt) : "memory");
}
__device__ __forceinline__ void mbar_wait(unsigned mb, unsigned parity) {
    unsigned done;
    asm volatile("{\n\t.reg .pred p;\n\t"
                 "mbarrier.try_wait.parity.acquire.cta.shared::cta.b64 p, [%1], %2;\n\t"
                 "selp.b32 %0, 1, 0, p;\n\t}"
                 : "=r"(done) : "r"(mb), "r"(parity) : "memory");
    if (!done) {
        asm volatile("{\n\t.reg .pred P;\n"
                     "W%=:\n\t"
                     "mbarrier.try_wait.parity.acquire.cta.shared::cta.b64 P, [%0], %1, 0x989680;\n\t"
                     "@P bra.uni D%=;\n\t"
                     "bra.uni W%=;\n"
                     "D%=:\n\t}"
                     :: "r"(mb), "r"(parity) : "memory");
    }
}
__device__ __forceinline__ void tma_issue(unsigned mb, unsigned dst, const void* src) {
    asm volatile("mbarrier.arrive.expect_tx.shared.b64 _, [%0], %1;"
                 :: "r"(mb), "r"((unsigned)CHBYTES) : "memory");
    asm volatile("cp.async.bulk.shared::cluster.global.mbarrier::complete_tx::bytes "
                 "[%0], [%1], %2, [%3];"
                 :: "r"(dst), "l"(src), "r"((unsigned)CHBYTES), "r"(mb) : "memory");
}

// ---------------- prep: build paired fused weight image ----------------
__global__ void prep_kernel(const float* __restrict__ eWh, const float* __restrict__ eWx,
                            const float* __restrict__ dWh, const float* __restrict__ dWx)
{
    int p  = blockIdx.x / KPAD;
    int kp = blockIdx.x % KPAD;
    int d  = threadIdx.x;
    const float* Wh = p ? dWh : eWh;
    const float* Wx = p ? dWx : eWx;
    int k0 = 2 * kp, k1 = 2 * kp + 1;
    float v0 = (k0 < D_) ? Wh[d * D_ + k0] : ((k0 < D_ + C_) ? Wx[d * C_ + (k0 - D_)] : 0.f);
    float v1 = (k1 < D_) ? Wh[d * D_ + k1] : ((k1 < D_ + C_) ? Wx[d * C_ + (k1 - D_)] : 0.f);
    g_Wp[p][kp][d] = make_float2(v0, v1);
}

// ---------------- main persistent kernel ----------------
extern "C" __global__ void __launch_bounds__(NTHR, 1)
seq2seq_kernel(const float* __restrict__ x,
               const float* __restrict__ ebx, const float* __restrict__ dbx,
               const float* __restrict__ dWy, const float* __restrict__ dby,
               float* __restrict__ out)
{
    extern __shared__ float sm[];
    float2* sW2  = (float2*)(sm + OFF_SW);
    float2* sh   = (float2*)(sm + OFF_SH);     // [kp][32] float2
    float*  sWy  = sm + OFF_SWY;
    float2* sbx2 = (float2*)(sm + OFF_SBX);
    float*  sby  = sm + OFF_SBY;
    float*  ytmp = sm + OFF_YT;

    const int tid  = threadIdx.x;
    const int lane = tid & 31;
    const int warp = tid >> 5;
    const int rowbase = blockIdx.x * RB;

    const int r0 = (tid & 7) * 4;        // 4 rows
    const int d0 = (tid >> 3) * 8;       // 8 outputs
    const int m0 = d0 >> 1;              // output k-pair base for h store

    const unsigned sW_u32 = smem_u32(sm) + OFF_SW * 4;
    const unsigned mb0    = smem_u32(sm) + OFF_MB * 4;
    const unsigned mb1    = mb0 + 8;

    const int xr = tid / 6, xc2 = tid % 6;    // x staging map (tid<192)

    // ---- init ----
    for (int i = tid; i < KPAD * RB; i += NTHR) sh[i] = make_float2(0.f, 0.f);
    for (int i = tid; i < K_ * D_; i += NTHR)   sWy[i] = dWy[i];
    sbx2[tid] = make_float2(ebx[tid], 0.f);
    if (tid < K_) sby[tid] = dby[tid];
    if (tid == 0) { mbar_init(mb0, 1); mbar_init(mb1, 1); }
    __syncthreads();
    if (tid < 192) {   // stage x_0 into aug rows
        const float2 v = *(const float2*)(x + ((size_t)0 * N_ + rowbase + xr) * C_ + 2 * xc2);
        sh[(128 + xc2) * RB + xr] = v;
    }
    if (tid == 0) {    // prime chunks 0,1 of step 0 (phase 0)
        tma_issue(mb0, sW_u32,           (const char*)g_Wp);
        tma_issue(mb1, sW_u32 + CHBYTES, (const char*)g_Wp + CHBYTES);
    }
    __syncthreads();

    unsigned par0 = 0, par1 = 0;
    ull acc[32];

    for (int t = 0; t < 2 * T_; ++t) {
        const bool dec = (t >= T_);

        if (t == T_) {
            sbx2[tid] = make_float2(dbx[tid], 0.f);
            __syncthreads();
        }

        // prefetch next x pair into regs (encoder epilogue will store it)
        float2 xv = make_float2(0.f, 0.f);
        if (!dec && (t + 1) < T_ && tid < 192)
            xv = *(const float2*)(x + ((size_t)(t + 1) * N_ + rowbase + xr) * C_ + 2 * xc2);

        // acc init = {bias, 0} for every (row, d)
        {
            const ull* bp = (const ull*)sbx2 + d0;
            ulonglong2 b0 = *(const ulonglong2*)(bp);
            ulonglong2 b1 = *(const ulonglong2*)(bp + 2);
            ulonglong2 b2 = *(const ulonglong2*)(bp + 4);
            ulonglong2 b3 = *(const ulonglong2*)(bp + 6);
            ull bias[8] = {b0.x, b0.y, b1.x, b1.y, b2.x, b2.y, b3.x, b3.y};
            #pragma unroll
            for (int i = 0; i < 4; ++i)
                #pragma unroll
                for (int j = 0; j < 8; ++j) acc[i * 8 + j] = bias[j];
        }

        const int ph_next = ((t + 1) >= T_) ? 1 : 0;

        // ---- GEMM over 8 chunks, TMA double-buffered ----
        #pragma unroll 1
        for (int c = 0; c < NCHK; ++c) {
            const int b = c & 1;
            if (b == 0) { mbar_wait(mb0, par0); par0 ^= 1; }
            else        { mbar_wait(mb1, par1); par1 ^= 1; }

            const ull* wb = (const ull*)(sW2 + b * (CH * D_)) + d0;
            const ull* hb = (const ull*)(sh + c * (CH * RB)) + r0;

            #pragma unroll 2
            for (int kk = 0; kk < CH; ++kk) {
                const ull* hp = hb + kk * RB;
                ulonglong2 hA = *(const ulonglong2*)(hp);
                ulonglong2 hB = *(const ulonglong2*)(hp + 2);
                const ull* wp = wb + kk * D_;
                ulonglong2 wA = *(const ulonglong2*)(wp);
                ulonglong2 wB = *(const ulonglong2*)(wp + 2);
                ulonglong2 wC = *(const ulonglong2*)(wp + 4);
                ulonglong2 wD = *(const ulonglong2*)(wp + 6);
                ull hr[4] = {hA.x, hA.y, hB.x, hB.y};
                ull wr[8] = {wA.x, wA.y, wB.x, wB.y, wC.x, wC.y, wD.x, wD.y};
                #pragma unroll
                for (int i = 0; i < 4; ++i)
                    #pragma unroll
                    for (int j = 0; j < 8; ++j)
                        ffma2(acc[i * 8 + j], hr[i], wr[j]);
            }
            __syncthreads();   // buffer b fully consumed by all threads

            if (tid == 0) {
                if (c < 6) {
                    tma_issue(b ? mb1 : mb0, sW_u32 + b * CHBYTES,
                              (const char*)g_Wp + ((size_t)(dec ? 1 : 0) * KPAD + (c + 2) * CH) * D_ * 8);
                } else if (c == 6) {
                    if (t + 1 < 2 * T_)
                        tma_issue(mb0, sW_u32,
                                  (const char*)g_Wp + (size_t)ph_next * KPAD * D_ * 8);
                } else {
                    if (t + 1 < 2 * T_)
                        tma_issue(mb1, sW_u32 + CHBYTES,
                                  (const char*)g_Wp + ((size_t)ph_next * KPAD + CH) * D_ * 8);
                }
            }
        }

        // ---- epilogue: h = relu(lo+hi), store paired into sh ----
        #pragma unroll
        for (int j2 = 0; j2 < 4; ++j2) {
            float2 v[4];
            #pragma unroll
            for (int i = 0; i < 4; ++i) {
                float lo, hi, lo2, hi2;
                unpack2(acc[i * 8 + 2 * j2],     lo,  hi);
                unpack2(acc[i * 8 + 2 * j2 + 1], lo2, hi2);
                v[i] = make_float2(fmaxf(lo + hi, 0.f), fmaxf(lo2 + hi2, 0.f));
            }
            float4* dst = (float4*)(sh + (m0 + j2) * RB + r0);
            dst[0] = make_float4(v[0].x, v[0].y, v[1].x, v[1].y);
            dst[1] = make_float4(v[2].x, v[2].y, v[3].x, v[3].y);
        }
        if (!dec && tid < 192) {
            // stage next aug: x_{t+1}, or SOS one-hot (col C-2=10 -> pair 5 = {1,0})
            float2 v = ((t + 1) < T_) ? xv
                       : ((xc2 == 5) ? make_float2(1.f, 0.f) : make_float2(0.f, 0.f));
            sh[(128 + xc2) * RB + xr] = v;
        }
        __syncthreads();

        // ---- decoder: y = h @ Wy^T + by, argmax, one-hot feedback ----
        if (dec) {
            const ull* hY = (const ull*)sh;
            const ull* wY = (const ull*)sWy;
            {   // pass A: k = warp (0..7), r = lane
                const int k = warp, r = lane;
                ull a = 0ull;
                #pragma unroll 4
                for (int m = 0; m < 128; ++m)
                    ffma2(a, hY[m * RB + r], wY[k * 128 + m]);
                float lo, hi; unpack2(a, lo, hi);
                ytmp[r * K_ + k] = lo + hi + sby[k];
            }
            if (tid < 128) {   // pass B: k = 8 + warp'
                const int k = 8 + warp, r = lane;
                ull a = 0ull;
                #pragma unroll 4
                for (int m = 0; m < 128; ++m)
                    ffma2(a, hY[m * RB + r], wY[k * 128 + m]);
                float lo, hi; unpack2(a, lo, hi);
                ytmp[r * K_ + k] = lo + hi + sby[k];
            }
            __syncthreads();

            int sel = 0;
            if (warp == 0) {
                const float* yr = ytmp + lane * K_;
                float v[12];
                #pragma unroll
                for (int q = 0; q < 3; ++q) {
                    float4 f = *(const float4*)(yr + 4 * q);
                    v[4 * q] = f.x; v[4 * q + 1] = f.y; v[4 * q + 2] = f.z; v[4 * q + 3] = f.w;
                }
                float best = v[0];
                #pragma unroll
                for (int q = 1; q < 12; ++q)
                    if (v[q] > best) { best = v[q]; sel = q; }
                float* og = out + ((size_t)(t - T_) * N_ + rowbase + lane) * K_;
                *(float4*)(og)     = make_float4(v[0], v[1], v[2],  v[3]);
                *(float4*)(og + 4) = make_float4(v[4], v[5], v[6],  v[7]);
                *(float4*)(og + 8) = make_float4(v[8], v[9], v[10], v[11]);
            }
            // zero aug rows 128..133 (pad rows 134/135 stay zero forever)
            if (tid < 192) sh[(128 + xc2) * RB + xr] = make_float2(0.f, 0.f);
            __syncthreads();
            if (warp == 0) {   // one-hot for next step
                float2 oh = (sel & 1) ? make_float2(0.f, 1.f) : make_float2(1.f, 0.f);
                sh[(128 + (sel >> 1)) * RB + lane] = oh;
            }
            // visibility for next step guaranteed by its per-chunk barriers
        }
    }
}

extern "C" void kernel_launch(void* const* d_in, const int* in_sizes, int n_in,
                              void* d_out, int out_size) {
    const float* x   = (const float*)d_in[0];
    const float* eWx = (const float*)d_in[1];
    const float* ebx = (const float*)d_in[2];
    const float* eWh = (const float*)d_in[3];
    const float* dWx = (const float*)d_in[6];
    const float* dbx = (const float*)d_in[7];
    const float* dWh = (const float*)d_in[8];
    const float* dWy = (const float*)d_in[9];
    const float* dby = (const float*)d_in[10];

    prep_kernel<<<2 * KPAD, D_>>>(eWh, eWx, dWh, dWx);

    cudaFuncSetAttribute(seq2seq_kernel,
                         cudaFuncAttributeMaxDynamicSharedMemorySize, SMEM_BYTES);
    seq2seq_kernel<<<NBLK, NTHR, SMEM_BYTES>>>(
        x, ebx, dbx, dWy, dby, (float*)d_out);
}